// round 3
// baseline (speedup 1.0000x reference)
#include <cuda_runtime.h>

#define NB 128      // batches
#define NP 27       // centers (3^3)
#define NN 8192     // points per batch
#define NS 512      // nsample
#define RAD2 0.0625f
#define NT 256      // threads per CTA
#define NWARP (NT / 32)

__global__ __launch_bounds__(NT) void ballgroup_kernel(
    const float* __restrict__ xyz,
    const float* __restrict__ centers,
    float* __restrict__ out)
{
    const int bp = blockIdx.x;          // 0 .. NB*NP-1
    const int b  = bp / NP;
    const int p  = bp - b * NP;

    const float cx = centers[p * 3 + 0];
    const float cy = centers[p * 3 + 1];
    const float cz = centers[p * 3 + 2];
    // c2 in the reference's association order (no fma)
    const float c2 = __fadd_rn(__fadd_rn(__fmul_rn(cx, cx), __fmul_rn(cy, cy)),
                               __fmul_rn(cz, cz));

    const float* pts = xyz + (size_t)b * (NN * 3);
    float* o = out + (size_t)bp * (NS * 3);

    __shared__ float s_pts[NT * 3];
    __shared__ int   s_wcnt[NWARP];
    __shared__ float s_first[3];

    const int tid  = threadIdx.x;
    const int lane = tid & 31;
    const int warp = tid >> 5;

    if (tid == 0) {
        // Default pad value: first_idx = 0 when no point matches (argmax of all-false)
        s_first[0] = __fsub_rn(pts[0], cx);
        s_first[1] = __fsub_rn(pts[1], cy);
        s_first[2] = __fsub_rn(pts[2], cz);
    }

    int base = 0;   // uniform across threads: slots assigned so far
    for (int chunk = 0; chunk < NN; chunk += NT) {
        __syncthreads();   // protect s_pts / s_wcnt from previous iteration readers
        #pragma unroll
        for (int k = 0; k < 3; k++)
            s_pts[k * NT + tid] = pts[chunk * 3 + k * NT + tid];
        __syncthreads();

        const float x = s_pts[tid * 3 + 0];
        const float y = s_pts[tid * 3 + 1];
        const float z = s_pts[tid * 3 + 2];

        // dist2 = (x2 + c2) - 2*xc, exactly as the reference (mul/add, no fma)
        const float x2 = __fadd_rn(__fadd_rn(__fmul_rn(x, x), __fmul_rn(y, y)),
                                   __fmul_rn(z, z));
        const float xc = __fadd_rn(__fadd_rn(__fmul_rn(cx, x), __fmul_rn(cy, y)),
                                   __fmul_rn(cz, z));
        const float d2 = __fsub_rn(__fadd_rn(x2, c2), __fmul_rn(2.0f, xc));

        const bool m = d2 < RAD2;
        const unsigned bal = __ballot_sync(0xffffffffu, m);
        if (lane == 0) s_wcnt[warp] = __popc(bal);
        __syncthreads();

        int off = base;
        int tot = 0;
        #pragma unroll
        for (int w = 0; w < NWARP; w++) {
            const int c = s_wcnt[w];
            if (w < warp) off += c;
            tot += c;
        }

        if (m) {
            const int slot = off + __popc(bal & ((1u << lane) - 1u));
            if (slot < NS) {
                const float ox = __fsub_rn(x, cx);
                const float oy = __fsub_rn(y, cy);
                const float oz = __fsub_rn(z, cz);
                o[slot * 3 + 0] = ox;
                o[slot * 3 + 1] = oy;
                o[slot * 3 + 2] = oz;
                if (slot == 0) {       // first matching point = pad value
                    s_first[0] = ox;
                    s_first[1] = oy;
                    s_first[2] = oz;
                }
            }
        }

        base += tot;                   // uniform update (all threads computed tot)
        if (base >= NS) break;         // all 512 slots filled; uniform exit
    }

    __syncthreads();                   // s_first final; scan writes ordered
    const int count = base < NS ? base : NS;
    const float f0 = s_first[0];
    const float f1 = s_first[1];
    const float f2 = s_first[2];

    // Coalesced pad fill of slots [count, NS)
    for (int i = count * 3 + tid; i < NS * 3; i += NT) {
        const int d = i % 3;
        o[i] = (d == 0) ? f0 : (d == 1) ? f1 : f2;
    }
}

extern "C" void kernel_launch(void* const* d_in, const int* in_sizes, int n_in,
                              void* d_out, int out_size)
{
    const float* xyz     = (const float*)d_in[0];   // [128, 8192, 3]
    const float* centers = (const float*)d_in[1];   // [1, 27, 3]
    float* out = (float*)d_out;                      // [3456, 512, 3]

    ballgroup_kernel<<<NB * NP, NT>>>(xyz, centers, out);
}

// round 8
// speedup vs baseline: 3.3408x; 3.3408x over previous
#include <cuda_runtime.h>

#define NB 128      // batches
#define NP 27       // centers (3^3)
#define NN 8192     // points per batch
#define NS 512      // nsample
#define RAD2 0.0625f
#define BOXLIM 0.501f   // conservative candidate box: max|c_d| + r + margin

// ---- static scratch (no runtime allocation allowed) ----
__device__ float g_cand[(size_t)NB * NN * 3];   // compacted candidate coords, order-preserving
__device__ int   g_cnt[NB];                      // candidates per batch

// ============================================================
// Kernel 1: per-batch order-preserving compaction of points with
// all |coord| <= BOXLIM. 1 CTA per batch, 512 threads.
// ============================================================
#define CT 512
#define CWARP (CT / 32)

__global__ __launch_bounds__(CT) void compact_kernel(const float* __restrict__ xyz)
{
    const int b = blockIdx.x;
    const float* pts = xyz + (size_t)b * (NN * 3);
    float* dst = g_cand + (size_t)b * (NN * 3);

    __shared__ int s_wcnt[CWARP];

    const int tid  = threadIdx.x;
    const int lane = tid & 31;
    const int warp = tid >> 5;

    int base = 0;
    for (int chunk = 0; chunk < NN; chunk += CT) {
        const int i = chunk + tid;
        const float x = pts[i * 3 + 0];
        const float y = pts[i * 3 + 1];
        const float z = pts[i * 3 + 2];

        const bool m = (fabsf(x) <= BOXLIM) && (fabsf(y) <= BOXLIM) && (fabsf(z) <= BOXLIM);
        const unsigned bal = __ballot_sync(0xffffffffu, m);

        __syncthreads();                       // prev-iteration readers of s_wcnt done
        if (lane == 0) s_wcnt[warp] = __popc(bal);
        __syncthreads();

        int off = base;
        int tot = 0;
        #pragma unroll
        for (int w = 0; w < CWARP; w++) {
            const int c = s_wcnt[w];
            if (w < warp) off += c;
            tot += c;
        }

        if (m) {
            const int slot = off + __popc(bal & ((1u << lane) - 1u));
            dst[slot * 3 + 0] = x;
            dst[slot * 3 + 1] = y;
            dst[slot * 3 + 2] = z;
        }
        base += tot;
    }

    if (tid == 0) g_cnt[b] = base;
}

// ============================================================
// Kernel 2: ball query + group over candidates only.
// 1 CTA per (batch, center). 256 threads.
// ============================================================
#define NT 256
#define NWARP (NT / 32)

__global__ __launch_bounds__(NT) void ballgroup_kernel(
    const float* __restrict__ xyz,
    const float* __restrict__ centers,
    float* __restrict__ out)
{
    const int bp = blockIdx.x;
    const int b  = bp / NP;
    const int p  = bp - b * NP;

    const float cx = centers[p * 3 + 0];
    const float cy = centers[p * 3 + 1];
    const float cz = centers[p * 3 + 2];
    // c2 in the reference's association order (no fma)
    const float c2 = __fadd_rn(__fadd_rn(__fmul_rn(cx, cx), __fmul_rn(cy, cy)),
                               __fmul_rn(cz, cz));

    const float* pts0 = xyz + (size_t)b * (NN * 3);      // for pad default (point 0)
    const float* src  = g_cand + (size_t)b * (NN * 3);   // candidates, original order
    const int cnt = g_cnt[b];
    float* o = out + (size_t)bp * (NS * 3);

    __shared__ int   s_wcnt[NWARP];
    __shared__ float s_first[3];

    const int tid  = threadIdx.x;
    const int lane = tid & 31;
    const int warp = tid >> 5;

    if (tid == 0) {
        // default pad: first_idx = 0 when no match (argmax of all-false)
        s_first[0] = __fsub_rn(pts0[0], cx);
        s_first[1] = __fsub_rn(pts0[1], cy);
        s_first[2] = __fsub_rn(pts0[2], cz);
    }

    int base = 0;
    for (int chunk = 0; chunk < cnt; chunk += NT) {
        const int i = chunk + tid;
        const bool valid = (i < cnt);
        const int ii = valid ? i : 0;
        const float x = src[ii * 3 + 0];
        const float y = src[ii * 3 + 1];
        const float z = src[ii * 3 + 2];

        // dist2 = (x2 + c2) - 2*xc, exactly as the reference (mul/add, no fma)
        const float x2 = __fadd_rn(__fadd_rn(__fmul_rn(x, x), __fmul_rn(y, y)),
                                   __fmul_rn(z, z));
        const float xc = __fadd_rn(__fadd_rn(__fmul_rn(cx, x), __fmul_rn(cy, y)),
                                   __fmul_rn(cz, z));
        const float d2 = __fsub_rn(__fadd_rn(x2, c2), __fmul_rn(2.0f, xc));

        const bool m = valid && (d2 < RAD2);
        const unsigned bal = __ballot_sync(0xffffffffu, m);

        __syncthreads();
        if (lane == 0) s_wcnt[warp] = __popc(bal);
        __syncthreads();

        int off = base;
        int tot = 0;
        #pragma unroll
        for (int w = 0; w < NWARP; w++) {
            const int c = s_wcnt[w];
            if (w < warp) off += c;
            tot += c;
        }

        if (m) {
            const int slot = off + __popc(bal & ((1u << lane) - 1u));
            if (slot < NS) {
                const float ox = __fsub_rn(x, cx);
                const float oy = __fsub_rn(y, cy);
                const float oz = __fsub_rn(z, cz);
                o[slot * 3 + 0] = ox;
                o[slot * 3 + 1] = oy;
                o[slot * 3 + 2] = oz;
                if (slot == 0) {
                    s_first[0] = ox;
                    s_first[1] = oy;
                    s_first[2] = oz;
                }
            }
        }

        base += tot;
        if (base >= NS) break;
    }

    __syncthreads();
    const int count = base < NS ? base : NS;
    const float f0 = s_first[0];
    const float f1 = s_first[1];
    const float f2 = s_first[2];

    // ---- pad fill of float range [count*3, NS*3) with repeating (f0,f1,f2) ----
    const int start = count * 3;                 // <= 1536
    const int head  = (4 - (start & 3)) & 3;     // scalars to reach 16B alignment

    if (tid < head && start + tid < NS * 3) {
        const int fi = start + tid;
        const int d = fi % 3;
        o[fi] = (d == 0) ? f0 : (d == 1) ? f1 : f2;
    }

    // vectorized body: float index fi = 4*v, pattern index = v % 3
    float4 pat[3];
    pat[0] = make_float4(f0, f1, f2, f0);
    pat[1] = make_float4(f1, f2, f0, f1);
    pat[2] = make_float4(f2, f0, f1, f2);

    const int vstart = (start + head) >> 2;
    float4* o4 = reinterpret_cast<float4*>(o);
    for (int v = vstart + tid; v < (NS * 3) / 4; v += NT) {
        o4[v] = pat[v % 3];
    }
}

extern "C" void kernel_launch(void* const* d_in, const int* in_sizes, int n_in,
                              void* d_out, int out_size)
{
    const float* xyz     = (const float*)d_in[0];   // [128, 8192, 3]
    const float* centers = (const float*)d_in[1];   // [1, 27, 3]
    float* out = (float*)d_out;                      // [3456, 512, 3]

    compact_kernel<<<NB, CT>>>(xyz);
    ballgroup_kernel<<<NB * NP, NT>>>(xyz, centers, out);
}